// round 17
// baseline (speedup 1.0000x reference)
#include <cuda_runtime.h>
#include <cuda_fp16.h>
#include <cstdint>

// Problem shape (fixed by the dataset)
#define BATCH 2
#define SEQ   2048
#define DIM   1024
#define NHEAD 16
#define DHEAD 64
#define MROWS (BATCH * SEQ)          // 4096
#define NQKV  (3 * DIM)              // 3072
#define KTOT  1024

// ---------------------------------------------------------------------------
// Scratch (allocation-free rule: __device__ globals), all single fp16
// ---------------------------------------------------------------------------
__device__ __half s_a[MROWS * KTOT];      // GEMM A: x, then attention out
__device__ __half s_wq[KTOT * NQKV];      // w_attn [1024,3072] natural layout
__device__ __half s_wp[KTOT * DIM];       // w_proj [1024,1024] natural layout
__device__ __half s_q[BATCH * NHEAD * SEQ * DHEAD];     // q*0.125, [bh,s,dh]
__device__ __half s_k[BATCH * NHEAD * SEQ * DHEAD];
__device__ __half s_v[BATCH * NHEAD * SEQ * DHEAD];

// ---------------------------------------------------------------------------
// PTX helpers (baseline ISA — compiles for sm_103)
// ---------------------------------------------------------------------------
__device__ __forceinline__ uint32_t smem_u32(const void* p) {
    uint32_t a;
    asm("{ .reg .u64 t; cvta.to.shared.u64 t, %1; cvt.u32.u64 %0, t; }"
        : "=r"(a) : "l"(p));
    return a;
}
__device__ __forceinline__ void ldsm4(uint32_t addr, uint32_t& r0, uint32_t& r1,
                                      uint32_t& r2, uint32_t& r3) {
    asm volatile("ldmatrix.sync.aligned.m8n8.x4.shared.b16 {%0,%1,%2,%3}, [%4];"
                 : "=r"(r0), "=r"(r1), "=r"(r2), "=r"(r3) : "r"(addr));
}
__device__ __forceinline__ void ldsm4t(uint32_t addr, uint32_t& r0, uint32_t& r1,
                                       uint32_t& r2, uint32_t& r3) {
    asm volatile("ldmatrix.sync.aligned.m8n8.x4.trans.shared.b16 {%0,%1,%2,%3}, [%4];"
                 : "=r"(r0), "=r"(r1), "=r"(r2), "=r"(r3) : "r"(addr));
}
__device__ __forceinline__ void mma_f16(float& c0, float& c1, float& c2, float& c3,
                                        uint32_t a0, uint32_t a1, uint32_t a2, uint32_t a3,
                                        uint32_t b0, uint32_t b1) {
    asm volatile("mma.sync.aligned.m16n8k16.row.col.f32.f16.f16.f32 "
                 "{%0,%1,%2,%3}, {%4,%5,%6,%7}, {%8,%9}, {%0,%1,%2,%3};"
                 : "+f"(c0), "+f"(c1), "+f"(c2), "+f"(c3)
                 : "r"(a0), "r"(a1), "r"(a2), "r"(a3), "r"(b0), "r"(b1));
}
__device__ __forceinline__ void cp16(uint32_t saddr, const void* g) {
    asm volatile("cp.async.cg.shared.global [%0], [%1], 16;"
                 :: "r"(saddr), "l"(g) : "memory");
}
__device__ __forceinline__ void cp_commit() {
    asm volatile("cp.async.commit_group;" ::: "memory");
}
template <int N>
__device__ __forceinline__ void cp_wait() {
    asm volatile("cp.async.wait_group %0;" :: "n"(N) : "memory");
}
__device__ __forceinline__ uint32_t packh_f(float a, float b) {
    __half2 p = __floats2half2_rn(a, b);
    return *(uint32_t*)&p;
}

// ---------------------------------------------------------------------------
// Fused prep: convert x, w_attn, w_proj fp32 -> fp16
// ---------------------------------------------------------------------------
#define XN4  (MROWS * KTOT / 4)
#define WAN4 (KTOT * NQKV / 4)
#define WPN4 (KTOT * DIM / 4)

__global__ __launch_bounds__(256) void convert_all_kernel(
    const float* __restrict__ x, const float* __restrict__ wa,
    const float* __restrict__ wpr, __half* __restrict__ dx,
    __half* __restrict__ dwa, __half* __restrict__ dwp)
{
    int i = blockIdx.x * 256 + threadIdx.x;
    const float* src;
    __half* dst;
    if (i < XN4) {
        src = x; dst = dx;
    } else if (i < XN4 + WAN4) {
        i -= XN4; src = wa; dst = dwa;
    } else {
        i -= XN4 + WAN4;
        if (i >= WPN4) return;
        src = wpr; dst = dwp;
    }
    float4 v = ((const float4*)src)[i];
    uint2 u = make_uint2(packh_f(v.x, v.y), packh_f(v.z, v.w));
    *(uint2*)(dst + (size_t)i * 4) = u;
}

// ---------------------------------------------------------------------------
// HMMA GEMM, fp16, 4 warps (2x2 grid), warp tile 64x64 — halved smem
// fragment-reload redundancy. BK=64, 3-stage cp.async, 1 barrier/iter,
// 2 CTAs/SM. D[M,N] = A @ B + bias (B natural [K,N] via ldmatrix.trans).
// MODE 0: QKV epilogue -> q/k/v coalesced [bh,s,dh] (q*0.125)
// MODE 1: plain fp32 out
// ---------------------------------------------------------------------------
#define BM 128
#define BN 128
#define BK 64
#define ROWB  144                // A: 128B data + 16B pad
#define ROWBB 272                // B: 256B data + 16B pad
#define NKT (KTOT / BK)          // 16
#define OFF_B   (128 * ROWB)     // 18432
#define STG_BYTES (OFF_B + 64 * ROWBB)   // 35840
#define NSTAGE 3
#define GSM_BYTES (NSTAGE * STG_BYTES)   // 107520/CTA; x2 CTAs = 215KB/SM

template <int MODE, int NB>
__global__ __launch_bounds__(128, 2) void tc_gemm_kernel(
    const __half* __restrict__ A, const __half* __restrict__ B,
    const float* __restrict__ bias, float* __restrict__ outp)
{
    extern __shared__ char gsm[];
    const uint32_t sb = smem_u32(gsm);

    const int tid  = threadIdx.x;
    const int w    = tid >> 5;
    const int lane = tid & 31;
    const int m0 = blockIdx.y * BM;
    const int n0 = blockIdx.x * BN;
    const int wm = (w >> 1) * 64;    // 2x2 warp grid
    const int wn = (w & 1) * 64;

    auto load_stage = [&](int kt, int stg) {
        const uint32_t s0 = sb + stg * STG_BYTES;
#pragma unroll
        for (int i = 0; i < 8; ++i) {
            const int c = tid + i * 128;          // 0..1023
            const int row = c >> 3, seg = c & 7;  // A: 128 rows x 8 segs
            cp16(s0 + row * ROWB + seg * 16,
                 A + (size_t)(m0 + row) * KTOT + kt * BK + seg * 8);
            const int kr = c >> 4, bs = c & 15;   // B: 64 k-rows x 16 segs
            cp16(s0 + OFF_B + kr * ROWBB + bs * 16,
                 B + (size_t)(kt * BK + kr) * NB + n0 + bs * 8);
        }
    };

    float acc[4][8][4];
#pragma unroll
    for (int i = 0; i < 4; ++i)
#pragma unroll
        for (int j = 0; j < 8; ++j)
#pragma unroll
            for (int e = 0; e < 4; ++e) acc[i][j][e] = 0.f;

    const int ar = lane & 15, ah = lane >> 4;
    const uint32_t aoffb = (uint32_t)((wm + ar) * ROWB + ah * 16);
    const uint32_t boffb = (uint32_t)((((lane & 7) + ((lane >> 3) & 1) * 8) * ROWBB) +
                                      (wn + ((lane >> 4) & 1) * 8) * 2);

    load_stage(0, 0);
    cp_commit();
    load_stage(1, 1);
    cp_commit();

    int stg = 0;
    for (int kt = 0; kt < NKT; ++kt) {
        if (kt + 1 < NKT) cp_wait<1>(); else cp_wait<0>();
        __syncthreads();

        if (kt + 2 < NKT) {
            int s2 = stg + 2; if (s2 >= NSTAGE) s2 -= NSTAGE;
            load_stage(kt + 2, s2);
            cp_commit();
        }

        const uint32_t s0 = sb + stg * STG_BYTES;
#pragma unroll
        for (int ks = 0; ks < 4; ++ks) {
            const uint32_t akoff = s0 + aoffb + ks * 32;
            const uint32_t bkoff = s0 + OFF_B + boffb + ks * 16 * ROWBB;

            uint32_t fa[4][4];
#pragma unroll
            for (int mt = 0; mt < 4; ++mt)
                ldsm4(akoff + mt * 16 * ROWB,
                      fa[mt][0], fa[mt][1], fa[mt][2], fa[mt][3]);
            uint32_t fb[4][4];       // 4 trans-ldsm = 64 n-cols
#pragma unroll
            for (int nb = 0; nb < 4; ++nb)
                ldsm4t(bkoff + nb * 32,
                       fb[nb][0], fb[nb][1], fb[nb][2], fb[nb][3]);

#pragma unroll
            for (int mt = 0; mt < 4; ++mt)
#pragma unroll
                for (int nt = 0; nt < 8; ++nt) {
                    const int nb = nt >> 1, p = nt & 1;
                    mma_f16(acc[mt][nt][0], acc[mt][nt][1], acc[mt][nt][2], acc[mt][nt][3],
                            fa[mt][0], fa[mt][1], fa[mt][2], fa[mt][3],
                            fb[nb][p * 2], fb[nb][p * 2 + 1]);
                }
        }
        if (++stg >= NSTAGE) stg = 0;
    }

    // epilogue
    const int erow = (lane >> 2);
    const int ecol = (lane & 3) * 2;
#pragma unroll
    for (int mt = 0; mt < 4; ++mt) {
#pragma unroll
        for (int nt = 0; nt < 8; ++nt) {
#pragma unroll
            for (int half = 0; half < 2; ++half) {
                const int row = m0 + wm + mt * 16 + erow + half * 8;
                const int col = n0 + wn + nt * 8 + ecol;
                float v0 = acc[mt][nt][half * 2 + 0] + bias[col];
                float v1 = acc[mt][nt][half * 2 + 1] + bias[col + 1];
                if (MODE == 0) {
                    const int bb = row >> 11, s = row & 2047;
                    const int part = col >> 10;
                    const int dd = col & 1023;
                    const int h = dd >> 6, hd = dd & 63;
                    const int bh = (bb << 4) + h;
                    if (part == 0) { v0 *= 0.125f; v1 *= 0.125f; }
                    const size_t base = ((size_t)bh * SEQ + s) * DHEAD + hd;
                    __half* dst = (part == 0) ? s_q : ((part == 1) ? s_k : s_v);
                    *(uint32_t*)(dst + base) = packh_f(v0, v1);
                } else {
                    *(float2*)(outp + (size_t)row * DIM + col) = make_float2(v0, v1);
                }
            }
        }
    }
}

// ---------------------------------------------------------------------------
// Tensor-core flash attention (unchanged from R16 — validated).
// ---------------------------------------------------------------------------
#define AROWB 144
#define AQ 0
#define AKV0 18432
#define AKV_STG 18432
#define AV_OFF 9216
#define ASM_BYTES (AKV0 + 3 * AKV_STG)   // 73728; x3 CTAs = 216KB/SM

__global__ __launch_bounds__(128, 3) void attn_tc_kernel()
{
    extern __shared__ char asmem[];
    const uint32_t sb = smem_u32(asmem);
    const int tid  = threadIdx.x;
    const int w    = tid >> 5;
    const int lane = tid & 31;
    const int qt   = (int)(gridDim.x - 1) - (int)blockIdx.x;
    const int bh   = blockIdx.y;
    const int q0   = qt * 128;

    const __half* Qg = s_q + (size_t)bh * SEQ * DHEAD;
    const __half* Kg = s_k + (size_t)bh * SEQ * DHEAD;
    const __half* Vg = s_v + (size_t)bh * SEQ * DHEAD;

    auto load_kv = [&](int kt, int stg) {
        const uint32_t s0 = sb + AKV0 + stg * AKV_STG;
        const int kv0 = kt * 64;
#pragma unroll
        for (int i = 0; i < 4; ++i) {
            const int c = tid + i * 128;
            const int row = c >> 3, seg = c & 7;
            const uint32_t so = row * AROWB + seg * 16;
            const size_t g = (size_t)(kv0 + row) * DHEAD + seg * 8;
            cp16(s0 + so, Kg + g);
            cp16(s0 + AV_OFF + so, Vg + g);
        }
    };

#pragma unroll
    for (int i = 0; i < 8; ++i) {
        const int c = tid + i * 128;
        const int row = c >> 3, seg = c & 7;
        const uint32_t so = row * AROWB + seg * 16;
        const size_t go = (size_t)(q0 + row) * DHEAD + seg * 8;
        *(uint4*)(asmem + AQ + so) = *(const uint4*)(Qg + go);
    }

    const int ar = lane & 15, ahh = lane >> 4;
    const int grp = lane >> 3, l8 = lane & 7;
    const int row0 = lane >> 2, coll = (lane & 3) * 2;
    const int trow = (lane & 7) + ((lane >> 3) & 1) * 8;
    const uint32_t tcol = ((lane >> 4) & 1) * 16;

    float m_run[4], l_run[4];
#pragma unroll
    for (int i = 0; i < 4; ++i) { m_run[i] = -1e30f; l_run[i] = 0.f; }
    float oacc[2][8][4];
#pragma unroll
    for (int mt = 0; mt < 2; ++mt)
#pragma unroll
        for (int nt = 0; nt < 8; ++nt)
#pragma unroll
            for (int e = 0; e < 4; ++e) oacc[mt][nt][e] = 0.f;

    const int ntiles = qt * 2 + 2;
    load_kv(0, 0);
    cp_commit();
    if (1 < ntiles) { load_kv(1, 1); cp_commit(); }

    int stg = 0;
    for (int kt = 0; kt < ntiles; ++kt) {
        if (kt + 1 < ntiles) cp_wait<1>(); else cp_wait<0>();
        __syncthreads();

        if (kt + 2 < ntiles) {
            int s2 = stg + 2; if (s2 >= NSTAGE) s2 -= NSTAGE;
            load_kv(kt + 2, s2);
            cp_commit();
        }

        const uint32_t kvb = sb + AKV0 + stg * AKV_STG;
        const int kv0 = kt * 64;

        float s[2][8][4];
#pragma unroll
        for (int mt = 0; mt < 2; ++mt)
#pragma unroll
            for (int nt = 0; nt < 8; ++nt)
#pragma unroll
                for (int e = 0; e < 4; ++e) s[mt][nt][e] = 0.f;

#pragma unroll
        for (int ks = 0; ks < 4; ++ks) {
            uint32_t kb[4][4];
#pragma unroll
            for (int nb = 0; nb < 4; ++nb) {
                const uint32_t bo = (uint32_t)(((grp >> 1) * 8 + l8 + nb * 16) * AROWB +
                                               (grp & 1) * 16 + ks * 32);
                ldsm4(kvb + bo, kb[nb][0], kb[nb][1], kb[nb][2], kb[nb][3]);
            }
            uint32_t qf[2][4];
#pragma unroll
            for (int mt = 0; mt < 2; ++mt) {
                const uint32_t ao = (uint32_t)((w * 32 + mt * 16 + ar) * AROWB +
                                               ahh * 16 + ks * 32);
                ldsm4(sb + AQ + ao, qf[mt][0], qf[mt][1], qf[mt][2], qf[mt][3]);
            }
#pragma unroll
            for (int mt = 0; mt < 2; ++mt)
#pragma unroll
                for (int nt = 0; nt < 8; ++nt) {
                    const int nb = nt >> 1, p = nt & 1;
                    mma_f16(s[mt][nt][0], s[mt][nt][1], s[mt][nt][2], s[mt][nt][3],
                            qf[mt][0], qf[mt][1], qf[mt][2], qf[mt][3],
                            kb[nb][p * 2], kb[nb][p * 2 + 1]);
                }
        }

        if (kt >= qt * 2) {
#pragma unroll
            for (int mt = 0; mt < 2; ++mt) {
                const int rbase = q0 + w * 32 + mt * 16 + row0;
#pragma unroll
                for (int nt = 0; nt < 8; ++nt) {
                    const int cb = kv0 + nt * 8 + coll;
                    if (cb > rbase)     s[mt][nt][0] = -10000.f;
                    if (cb + 1 > rbase) s[mt][nt][1] = -10000.f;
                    if (cb > rbase + 8)     s[mt][nt][2] = -10000.f;
                    if (cb + 1 > rbase + 8) s[mt][nt][3] = -10000.f;
                }
            }
        }

        float corr[4];
#pragma unroll
        for (int slot = 0; slot < 4; ++slot) {
            const int mt = slot >> 1, h2 = slot & 1;
            float tm = -1e30f;
#pragma unroll
            for (int nt = 0; nt < 8; ++nt)
                tm = fmaxf(tm, fmaxf(s[mt][nt][h2 * 2], s[mt][nt][h2 * 2 + 1]));
            tm = fmaxf(tm, __shfl_xor_sync(0xffffffffu, tm, 1));
            tm = fmaxf(tm, __shfl_xor_sync(0xffffffffu, tm, 2));
            const float mnew = fmaxf(m_run[slot], tm);
            corr[slot] = __expf(m_run[slot] - mnew);
            m_run[slot] = mnew;
            l_run[slot] *= corr[slot];
        }
#pragma unroll
        for (int mt = 0; mt < 2; ++mt)
#pragma unroll
            for (int nt = 0; nt < 8; ++nt) {
                oacc[mt][nt][0] *= corr[mt * 2];
                oacc[mt][nt][1] *= corr[mt * 2];
                oacc[mt][nt][2] *= corr[mt * 2 + 1];
                oacc[mt][nt][3] *= corr[mt * 2 + 1];
            }

        uint32_t pf[2][8][2];
#pragma unroll
        for (int mt = 0; mt < 2; ++mt)
#pragma unroll
            for (int nt = 0; nt < 8; ++nt) {
                const float p0 = __expf(s[mt][nt][0] - m_run[mt * 2]);
                const float p1 = __expf(s[mt][nt][1] - m_run[mt * 2]);
                const float p2 = __expf(s[mt][nt][2] - m_run[mt * 2 + 1]);
                const float p3 = __expf(s[mt][nt][3] - m_run[mt * 2 + 1]);
                l_run[mt * 2]     += p0 + p1;
                l_run[mt * 2 + 1] += p2 + p3;
                pf[mt][nt][0] = packh_f(p0, p1);
                pf[mt][nt][1] = packh_f(p2, p3);
            }

#pragma unroll
        for (int ks = 0; ks < 4; ++ks) {
            uint32_t vb[4][4];
#pragma unroll
            for (int nb = 0; nb < 4; ++nb) {
                const uint32_t bo = (uint32_t)((trow + ks * 16) * AROWB + tcol + nb * 32);
                ldsm4t(kvb + AV_OFF + bo, vb[nb][0], vb[nb][1], vb[nb][2], vb[nb][3]);
            }
#pragma unroll
            for (int mt = 0; mt < 2; ++mt)
#pragma unroll
                for (int nt = 0; nt < 8; ++nt) {
                    const int nb = nt >> 1, p = nt & 1;
                    mma_f16(oacc[mt][nt][0], oacc[mt][nt][1], oacc[mt][nt][2], oacc[mt][nt][3],
                            pf[mt][ks * 2][0], pf[mt][ks * 2][1],
                            pf[mt][ks * 2 + 1][0], pf[mt][ks * 2 + 1][1],
                            vb[nb][p * 2], vb[nb][p * 2 + 1]);
                }
        }
        if (++stg >= NSTAGE) stg = 0;
    }

    float inv[4];
#pragma unroll
    for (int slot = 0; slot < 4; ++slot) {
        float lt = l_run[slot];
        lt += __shfl_xor_sync(0xffffffffu, lt, 1);
        lt += __shfl_xor_sync(0xffffffffu, lt, 2);
        inv[slot] = 1.f / lt;
    }
    const int b = bh >> 4, h = bh & 15;
#pragma unroll
    for (int mt = 0; mt < 2; ++mt) {
#pragma unroll
        for (int half = 0; half < 2; ++half) {
            const size_t orow = (size_t)b * SEQ + q0 + w * 32 + mt * 16 + row0 + half * 8;
            const float iv = inv[mt * 2 + half];
#pragma unroll
            for (int nt = 0; nt < 8; ++nt) {
                const int col = h * DHEAD + nt * 8 + coll;
                const float v0 = oacc[mt][nt][half * 2 + 0] * iv;
                const float v1 = oacc[mt][nt][half * 2 + 1] * iv;
                *(uint32_t*)(s_a + orow * DIM + col) = packh_f(v0, v1);
            }
        }
    }
}

// ---------------------------------------------------------------------------
extern "C" void kernel_launch(void* const* d_in, const int* in_sizes, int n_in,
                              void* d_out, int out_size)
{
    const float* x      = (const float*)d_in[0];
    const float* w_attn = (const float*)d_in[1];
    const float* b_attn = (const float*)d_in[2];
    const float* w_proj = (const float*)d_in[3];
    const float* b_proj = (const float*)d_in[4];
    float* out = (float*)d_out;

    __half *xa, *wq, *wp;
    cudaGetSymbolAddress((void**)&xa, s_a);
    cudaGetSymbolAddress((void**)&wq, s_wq);
    cudaGetSymbolAddress((void**)&wp, s_wp);

    cudaFuncSetAttribute((tc_gemm_kernel<0, NQKV>),
                         cudaFuncAttributeMaxDynamicSharedMemorySize, GSM_BYTES);
    cudaFuncSetAttribute((tc_gemm_kernel<1, DIM>),
                         cudaFuncAttributeMaxDynamicSharedMemorySize, GSM_BYTES);
    cudaFuncSetAttribute(attn_tc_kernel,
                         cudaFuncAttributeMaxDynamicSharedMemorySize, ASM_BYTES);

    // 1) fused convert: x, w_attn, w_proj -> fp16
    const int total4 = XN4 + WAN4 + WPN4;
    convert_all_kernel<<<(total4 + 255) / 256, 256>>>(x, w_attn, w_proj, xa, wq, wp);
    // 2) QKV GEMM (4 warps, 64x64 warp tiles) -> q/k/v fp16 [bh,s,dh]
    tc_gemm_kernel<0, NQKV><<<dim3(NQKV / BN, MROWS / BM), 128, GSM_BYTES>>>(
        xa, wq, b_attn, nullptr);
    // 3) tensor-core flash attention -> writes s_a (fp16)
    attn_tc_kernel<<<dim3(SEQ / 128, BATCH * NHEAD), 128, ASM_BYTES>>>();
    // 4) output projection
    tc_gemm_kernel<1, DIM><<<dim3(DIM / BN, MROWS / BM), 128, GSM_BYTES>>>(
        xa, wp, b_proj, out);
}